// round 15
// baseline (speedup 1.0000x reference)
#include <cuda_runtime.h>

#define BB 8192
#define TT 256
#define FF 16
#define HH 8
#define FUT 8

typedef unsigned long long u64;

__device__ __forceinline__ float tanhm(float x) {
    float y;
    asm("tanh.approx.f32 %0, %1;" : "=f"(y) : "f"(x));
    return y;
}
__device__ __forceinline__ float sigm(float x) {
    return fmaf(0.5f, tanhm(0.5f * x), 0.5f);
}
__device__ __forceinline__ u64 ffma2(u64 a, u64 b, u64 c) {
    u64 d;
    asm("fma.rn.f32x2 %0, %1, %2, %3;" : "=l"(d) : "l"(a), "l"(b), "l"(c));
    return d;
}
__device__ __forceinline__ u64 pack2(float lo, float hi) {
    u64 r;
    asm("mov.b64 %0, {%1, %2};" : "=l"(r) : "f"(lo), "f"(hi));
    return r;
}
__device__ __forceinline__ float hsum2(u64 v) {
    float lo, hi;
    asm("mov.b64 {%0, %1}, %2;" : "=f"(lo), "=f"(hi) : "l"(v));
    return lo + hi;
}
__device__ __forceinline__ float2 unpack2(u64 v) {
    float lo, hi;
    asm("mov.b64 {%0, %1}, %2;" : "=f"(lo), "=f"(hi) : "l"(v));
    return make_float2(lo, hi);
}
__device__ __forceinline__ void cpa16(unsigned dst, const void* src) {
    asm volatile("cp.async.ca.shared.global [%0], [%1], 16;\n"
                 :: "r"(dst), "l"(src) : "memory");
}
__device__ __forceinline__ void cpa_commit() {
    asm volatile("cp.async.commit_group;\n" ::: "memory");
}
__device__ __forceinline__ void cpa_wait3() {
    asm volatile("cp.async.wait_group 3;\n" ::: "memory");
}

// Layer-split warp specialization. 128-thread blocks, 16 elements each.
// Warps 0-1: layer-1 recurrence (x via cp.async ring, W1/U1 smem).
// Warps 2-3: layer-2 recurrence, one timestep behind, reading h1 from a
// 2-slot smem ring (padded, conflict-free). One __syncthreads per step.
// Per-warp work and registers halve vs R14 while warps/SMSP doubles.

__global__ __launch_bounds__(128) void LSTM_91122026152229_kernel(
    const float* __restrict__ past,   // [B,T,F]
    const float* __restrict__ fut,    // [B,FUT]
    const float* __restrict__ W1, const float* __restrict__ U1, const float* __restrict__ b1,
    const float* __restrict__ W2, const float* __restrict__ U2, const float* __restrict__ b2,
    const float* __restrict__ Wd1, const float* __restrict__ bd1,
    const float* __restrict__ Wd2, const float* __restrict__ bd2,
    const float* __restrict__ Wo, const float* __restrict__ bo,
    float* __restrict__ out)          // [B,4]
{
    __shared__ ulonglong2 sW1if[8 * 8], sW1go[8 * 8];   // k2=0..7
    __shared__ ulonglong2 sU1if[4 * 8], sU1go[4 * 8];   // k2=0..3
    __shared__ ulonglong2 sW2if[4 * 8], sW2go[4 * 8];
    __shared__ ulonglong2 sU2if[4 * 8], sU2go[4 * 8];
    // x ring: 4 slots x 16 elems x 20 floats (80B stride, conflict-free)
    __shared__ __align__(16) float sx[4 * 16 * 20];
    // h1 ring: 2 slots x 16 elems x 12 floats (48B stride: conflict-free STS
    // and 16B-aligned rows for packed LDS.128 pair loads)
    __shared__ __align__(16) float sh1[2 * 16 * 12];

    const int tid = threadIdx.x;

    // repack W1 (512 floats): src i = f*32 + g*8 + u
    for (int i = tid; i < 512; i += 128) {
        int f = i >> 5, r = i & 31, gg = r >> 3, uu = r & 7;
        int k2 = f >> 1, odd = f & 1;
        float v = W1[i];
        if (gg < 2)
            ((float*)sW1if)[((k2 * 8 + uu) << 2) + gg * 2 + odd] = v;
        else
            ((float*)sW1go)[((k2 * 8 + uu) << 2) + (gg - 2) * 2 + odd] = v;
    }
    // repack U1, W2, U2 (256 floats each)
    for (int i = tid; i < 256; i += 128) {
        int k = i >> 5, r = i & 31, gg = r >> 3, uu = r & 7;
        int k2 = k >> 1, odd = k & 1;
        int fo = ((k2 * 8 + uu) << 2) + ((gg & 1) * 2) + odd;
        float vU1 = U1[i], vW2 = W2[i], vU2 = U2[i];
        if (gg < 2) {
            ((float*)sU1if)[fo] = vU1;
            ((float*)sW2if)[fo] = vW2;
            ((float*)sU2if)[fo] = vU2;
        } else {
            ((float*)sU1go)[fo] = vU1;
            ((float*)sW2go)[fo] = vW2;
            ((float*)sU2go)[fo] = vU2;
        }
    }

    const int wid   = tid >> 5;
    const bool isL1 = (wid < 2);
    const int u     = tid & 7;
    const int gl    = (tid & 31) >> 3;       // group within warp: 0..3
    const int base8 = (tid & 31) & 24;
    // block-local element pair for this thread's group
    const int elw   = isL1 ? (8 * wid + 2 * gl) : (8 * (wid - 2) + 2 * gl);
    const int eA    = blockIdx.x * 16 + elw;      // global elem A
    const int eB    = eA + 1;

    // x producer mapping (layer-1 threads, tid<64): elem tid>>2, 16B chunk tid&3
    const int pe = tid >> 2;
    const int pq = tid & 3;
    const float* gsrc = past + (size_t)(blockIdx.x * 16 + pe) * (TT * FF) + pq * 4;
    const unsigned sxa  = (unsigned)__cvta_generic_to_shared(sx);
    const unsigned pdst = sxa + (unsigned)(pe * 20 + pq * 4) * 4u;

    if (tid < 64) {
        #pragma unroll
        for (int s = 0; s < 3; s++) {
            cpa16(pdst + (unsigned)(s * 320 * 4), gsrc + s * 16);
            cpa_commit();
        }
    }

    // per-role biases
    const float* bsrc = isL1 ? b1 : b2;
    const float bi = bsrc[u], bf = bsrc[u + 8], bg = bsrc[u + 16], bq = bsrc[u + 24];

    // recurrent state
    float cA = 0.f, cB = 0.f;            // c1 (L1 warps) or c2 (L2 warps)
    u64 hpA[4], hpB[4];                  // own-layer h pairs (h1 or h2)
    #pragma unroll
    for (int j = 0; j < 4; j++) { hpA[j] = 0ULL; hpB[j] = 0ULL; }

    __syncthreads();   // weights + preload visible

    #pragma unroll 1
    for (int tt = 0; tt <= TT; tt++) {
        __syncthreads();

        if (isL1) {
            if (tt < TT) {
                // produce x for step tt+3; consume x[tt]
                const int tn = (tt + 3 < TT) ? (tt + 3) : (TT - 1);
                cpa16(pdst + (unsigned)(((tt + 3) & 3) * 320 * 4), gsrc + tn * 16);
                cpa_commit();
                cpa_wait3();
                __syncwarp();

                const float* xs = sx + (tt & 3) * 320;
                const ulonglong2* xAp = (const ulonglong2*)(xs + elw * 20);
                const ulonglong2* xBp = (const ulonglong2*)(xs + (elw + 1) * 20);
                const ulonglong2 xA0 = xAp[0], xA1 = xAp[1], xA2 = xAp[2], xA3 = xAp[3];
                const ulonglong2 xB0 = xBp[0], xB1 = xBp[1], xB2 = xBp[2], xB3 = xBp[3];
                const u64 xqA[8] = { xA0.x, xA0.y, xA1.x, xA1.y, xA2.x, xA2.y, xA3.x, xA3.y };
                const u64 xqB[8] = { xB0.x, xB0.y, xB1.x, xB1.y, xB2.x, xB2.y, xB3.x, xB3.y };

                u64 aiA = 0, afA = 0, agA = 0, aoA = 0;
                u64 aiB = 0, afB = 0, agB = 0, aoB = 0;
                #pragma unroll
                for (int k2 = 0; k2 < 8; k2++) {
                    const ulonglong2 wif = sW1if[k2 * 8 + u];
                    const ulonglong2 wgo = sW1go[k2 * 8 + u];
                    const u64 xA = xqA[k2], xB = xqB[k2];
                    aiA = ffma2(xA, wif.x, aiA);  aiB = ffma2(xB, wif.x, aiB);
                    afA = ffma2(xA, wif.y, afA);  afB = ffma2(xB, wif.y, afB);
                    agA = ffma2(xA, wgo.x, agA);  agB = ffma2(xB, wgo.x, agB);
                    aoA = ffma2(xA, wgo.y, aoA);  aoB = ffma2(xB, wgo.y, aoB);
                }
                #pragma unroll
                for (int k2 = 0; k2 < 4; k2++) {
                    const ulonglong2 wif = sU1if[k2 * 8 + u];
                    const ulonglong2 wgo = sU1go[k2 * 8 + u];
                    const u64 hA = hpA[k2], hB = hpB[k2];
                    aiA = ffma2(hA, wif.x, aiA);  aiB = ffma2(hB, wif.x, aiB);
                    afA = ffma2(hA, wif.y, afA);  afB = ffma2(hB, wif.y, afB);
                    agA = ffma2(hA, wgo.x, agA);  agB = ffma2(hB, wgo.x, agB);
                    aoA = ffma2(hA, wgo.y, aoA);  aoB = ffma2(hB, wgo.y, aoB);
                }
                float h1A, h1B;
                {
                    const float ziA = hsum2(aiA) + bi, zfA = hsum2(afA) + bf;
                    const float zgA = hsum2(agA) + bg, zoA = hsum2(aoA) + bq;
                    cA = fmaf(sigm(zfA), cA, sigm(ziA) * tanhm(zgA));
                    h1A = sigm(zoA) * tanhm(cA);
                    const float ziB = hsum2(aiB) + bi, zfB = hsum2(afB) + bf;
                    const float zgB = hsum2(agB) + bg, zoB = hsum2(aoB) + bq;
                    cB = fmaf(sigm(zfB), cB, sigm(ziB) * tanhm(zgB));
                    h1B = sigm(zoB) * tanhm(cB);
                }
                // own-recurrence pairs via shfl
                #pragma unroll
                for (int k2 = 0; k2 < 4; k2++) {
                    const float aA = __shfl_sync(0xffffffffu, h1A, base8 + 2 * k2);
                    const float bA2 = __shfl_sync(0xffffffffu, h1A, base8 + 2 * k2 + 1);
                    const float aB = __shfl_sync(0xffffffffu, h1B, base8 + 2 * k2);
                    const float bB2 = __shfl_sync(0xffffffffu, h1B, base8 + 2 * k2 + 1);
                    hpA[k2] = pack2(aA, bA2);
                    hpB[k2] = pack2(aB, bB2);
                }
                // handoff to layer-2 warps
                float* hw = sh1 + (tt & 1) * 192;
                hw[elw * 12 + u]       = h1A;
                hw[(elw + 1) * 12 + u] = h1B;
            }
        } else {
            if (tt >= 1) {
                // read h1(tt-1) pairs, already packed, from the ring
                const float* hr = sh1 + ((tt - 1) & 1) * 192;
                const ulonglong2 pA0 = *(const ulonglong2*)(hr + elw * 12);
                const ulonglong2 pA1 = *(const ulonglong2*)(hr + elw * 12 + 4);
                const ulonglong2 pB0 = *(const ulonglong2*)(hr + (elw + 1) * 12);
                const ulonglong2 pB1 = *(const ulonglong2*)(hr + (elw + 1) * 12 + 4);
                const u64 h1A[4] = { pA0.x, pA0.y, pA1.x, pA1.y };
                const u64 h1B[4] = { pB0.x, pB0.y, pB1.x, pB1.y };

                u64 yiA = 0, yfA = 0, ygA = 0, yoA = 0;
                u64 yiB = 0, yfB = 0, ygB = 0, yoB = 0;
                #pragma unroll
                for (int k2 = 0; k2 < 4; k2++) {
                    const ulonglong2 wif = sW2if[k2 * 8 + u];
                    const ulonglong2 wgo = sW2go[k2 * 8 + u];
                    const u64 hA = h1A[k2], hB = h1B[k2];
                    yiA = ffma2(hA, wif.x, yiA);  yiB = ffma2(hB, wif.x, yiB);
                    yfA = ffma2(hA, wif.y, yfA);  yfB = ffma2(hB, wif.y, yfB);
                    ygA = ffma2(hA, wgo.x, ygA);  ygB = ffma2(hB, wgo.x, ygB);
                    yoA = ffma2(hA, wgo.y, yoA);  yoB = ffma2(hB, wgo.y, yoB);
                }
                #pragma unroll
                for (int k2 = 0; k2 < 4; k2++) {
                    const ulonglong2 wif = sU2if[k2 * 8 + u];
                    const ulonglong2 wgo = sU2go[k2 * 8 + u];
                    const u64 hA = hpA[k2], hB = hpB[k2];
                    yiA = ffma2(hA, wif.x, yiA);  yiB = ffma2(hB, wif.x, yiB);
                    yfA = ffma2(hA, wif.y, yfA);  yfB = ffma2(hB, wif.y, yfB);
                    ygA = ffma2(hA, wgo.x, ygA);  ygB = ffma2(hB, wgo.x, ygB);
                    yoA = ffma2(hA, wgo.y, yoA);  yoB = ffma2(hB, wgo.y, yoB);
                }
                float h2A, h2B;
                {
                    const float ziA = hsum2(yiA) + bi, zfA = hsum2(yfA) + bf;
                    const float zgA = hsum2(ygA) + bg, zoA = hsum2(yoA) + bq;
                    cA = fmaf(sigm(zfA), cA, sigm(ziA) * tanhm(zgA));
                    h2A = sigm(zoA) * tanhm(cA);
                    const float ziB = hsum2(yiB) + bi, zfB = hsum2(yfB) + bf;
                    const float zgB = hsum2(ygB) + bg, zoB = hsum2(yoB) + bq;
                    cB = fmaf(sigm(zfB), cB, sigm(ziB) * tanhm(zgB));
                    h2B = sigm(zoB) * tanhm(cB);
                }
                #pragma unroll
                for (int k2 = 0; k2 < 4; k2++) {
                    const float aA = __shfl_sync(0xffffffffu, h2A, base8 + 2 * k2);
                    const float bA2 = __shfl_sync(0xffffffffu, h2A, base8 + 2 * k2 + 1);
                    const float aB = __shfl_sync(0xffffffffu, h2B, base8 + 2 * k2);
                    const float bB2 = __shfl_sync(0xffffffffu, h2B, base8 + 2 * k2 + 1);
                    hpA[k2] = pack2(aA, bA2);
                    hpB[k2] = pack2(aB, bB2);
                }
            }
        }
    }

    // ---- MLP head: layer-2 warps only ----
    if (!isL1) {
        float h2sA[8], h2sB[8];
        #pragma unroll
        for (int k2 = 0; k2 < 4; k2++) {
            const float2 pA = unpack2(hpA[k2]);
            const float2 pB = unpack2(hpB[k2]);
            h2sA[2 * k2] = pA.x; h2sA[2 * k2 + 1] = pA.y;
            h2sB[2 * k2] = pB.x; h2sB[2 * k2 + 1] = pB.y;
        }

        float d1A = bd1[u], d1B = d1A;
        #pragma unroll
        for (int k = 0; k < 8; k++) {
            const float wk = Wd1[k * 8 + u];
            d1A = fmaf(h2sA[k], wk, d1A);
            d1B = fmaf(h2sB[k], wk, d1B);
        }
        const float* __restrict__ fpA = fut + (size_t)eA * FUT;
        const float* __restrict__ fpB = fut + (size_t)eB * FUT;
        #pragma unroll
        for (int k = 0; k < 8; k++) {
            const float wk = Wd1[(8 + k) * 8 + u];
            d1A = fmaf(fpA[k], wk, d1A);
            d1B = fmaf(fpB[k], wk, d1B);
        }
        d1A = fmaxf(d1A, 0.f);
        d1B = fmaxf(d1B, 0.f);

        float d2A = bd2[u], d2B = d2A;
        #pragma unroll
        for (int k = 0; k < 8; k++) {
            const float wk = Wd2[k * 8 + u];
            const float d1kA = __shfl_sync(0xffffffffu, d1A, base8 + k);
            const float d1kB = __shfl_sync(0xffffffffu, d1B, base8 + k);
            d2A = fmaf(d1kA, wk, d2A);
            d2B = fmaf(d1kB, wk, d2B);
        }
        d2A = fmaxf(d2A, 0.f);
        d2B = fmaxf(d2B, 0.f);

        float oA = (u < 4) ? bo[u] : 0.f;
        float oB = oA;
        #pragma unroll
        for (int k = 0; k < 8; k++) {
            const float wk = (u < 4) ? Wo[k * 4 + u] : 0.f;
            const float d2kA = __shfl_sync(0xffffffffu, d2A, base8 + k);
            const float d2kB = __shfl_sync(0xffffffffu, d2B, base8 + k);
            oA = fmaf(d2kA, wk, oA);
            oB = fmaf(d2kB, wk, oB);
        }
        if (u < 4) {
            out[(size_t)eA * 4 + u] = oA;
            out[(size_t)eB * 4 + u] = oB;
        }
    }
}

extern "C" void kernel_launch(void* const* d_in, const int* in_sizes, int n_in,
                              void* d_out, int out_size) {
    const float* past = (const float*)d_in[1];
    const float* fut  = (const float*)d_in[2];
    const float* W1   = (const float*)d_in[3];
    const float* U1   = (const float*)d_in[4];
    const float* b1   = (const float*)d_in[5];
    const float* W2   = (const float*)d_in[6];
    const float* U2   = (const float*)d_in[7];
    const float* b2   = (const float*)d_in[8];
    const float* Wd1  = (const float*)d_in[9];
    const float* bd1  = (const float*)d_in[10];
    const float* Wd2  = (const float*)d_in[11];
    const float* bd2  = (const float*)d_in[12];
    const float* Wo   = (const float*)d_in[13];
    const float* bo   = (const float*)d_in[14];

    // 512 blocks x 128 threads: 16 elems/block, layer-split warps
    LSTM_91122026152229_kernel<<<BB / 16, 128>>>(
        past, fut, W1, U1, b1, W2, U2, b2, Wd1, bd1, Wd2, bd2, Wo, bo,
        (float*)d_out);
}